// round 13
// baseline (speedup 1.0000x reference)
#include <cuda_runtime.h>

// entmax-1.5 attention, B=8, S=2048, D=128, fp32.
// One block = 16 query rows of one batch, 512 threads (16 warps).
// Round-11 structure (647 us) + software-pipelined global loads:
//   1) QK: z[16][2048] = 0.5*Q K^T in SMEM. 4q x 4k register tile, 512-k K tile
//      staged transposed with coalesced LDG + XOR swizzle; NEXT K slice
//      prefetched into registers during compute.
//   2) bisection for tau: one warp per row, 64 z-values/thread, 22 iters.
//      (first V tile LDG issued before this phase, hidden under it)
//   3) PV: O = w V. 8q x 4d register tile, 8-way k-split, 128-k V tiles with
//      register prefetch, 3-stage conflict-free SMEM tree reduction.

#define SLEN 2048
#define DDIM 128
#define TQ   16
#define ZSTR 2052   // z row stride (floats)
#define KSTR2 516   // transposed K tile row stride (floats), 512 k + pad
#define QTSTR 20    // transposed Q tile row stride (floats)
#define NITER 22
#define NTHR 512

__device__ __forceinline__ void fma4(float4& o, float s, const float4& v) {
    o.x += s * v.x; o.y += s * v.y; o.z += s * v.z; o.w += s * v.w;
}
__device__ __forceinline__ void add4(float4& o, const float4& v) {
    o.x += v.x; o.y += v.y; o.z += v.z; o.w += v.w;
}

__global__ __launch_bounds__(NTHR, 1)
void entmax_attn_kernel(const float* __restrict__ Q,
                        const float* __restrict__ K,
                        const float* __restrict__ V,
                        float* __restrict__ O) {
    extern __shared__ float sm[];
    float* zsh = sm;                          // 16 * 2052 = 32,832 floats
    float* ks  = sm + TQ * ZSTR;              // 32 * 516  = 16,512 floats (reused: V stage / reduction)
    float* qT  = ks + 32 * KSTR2;             // 128 * 20  =  2,560 floats

    const int tid  = threadIdx.x;
    const int lane = tid & 31;
    const int warp = tid >> 5;
    const int b    = blockIdx.y;
    const int qt   = blockIdx.x;

    const float* Qb = Q + ((size_t)b * SLEN + qt * TQ) * DDIM;
    const float* Kb = K + (size_t)b * SLEN * DDIM;
    const float* Vb = V + (size_t)b * SLEN * DDIM;
    float*       Ob = O + ((size_t)b * SLEN + qt * TQ) * DDIM;

    // ---- stage Q tile transposed qT[d][q], pre-scaled by (alpha-1)=0.5 ----
    {
        int q  = tid >> 5;       // 0..15
        int d4 = tid & 31;       // 0..31
        float4 v = *(const float4*)(Qb + q * DDIM + d4 * 4);
        qT[(d4 * 4 + 0) * QTSTR + q] = 0.5f * v.x;
        qT[(d4 * 4 + 1) * QTSTR + q] = 0.5f * v.y;
        qT[(d4 * 4 + 2) * QTSTR + q] = 0.5f * v.z;
        qT[(d4 * 4 + 3) * QTSTR + q] = 0.5f * v.w;
    }

    // =========================== Phase 1: QK ===========================
    // 4q x 4k per thread: qg = tid>>7 (4 q rows), kg4 = (tid&127)*4 (4 k cols).
    const int qg  = tid >> 7;
    const int kg4 = (tid & 127) * 4;
    // staging: 8 lanes cover one K-row 128B slice; 4 rows per warp-LDG (coalesced).
    const int d16  = (lane & 7) * 4;   // d chunk start within 32-float slice
    const int ksub = lane >> 3;        // 0..3
    const int kbase = warp * 32 + ksub;

    float4 pf[8];
    // prefetch first K slice (kb=0, db=0)
    #pragma unroll
    for (int r = 0; r < 8; r++)
        pf[r] = *(const float4*)(Kb + (size_t)(kbase + r * 4) * DDIM + d16);

    for (int kb = 0; kb < SLEN; kb += 512) {
        float4 a0 = {0,0,0,0}, a1 = {0,0,0,0}, a2 = {0,0,0,0}, a3 = {0,0,0,0};
        for (int db = 0; db < DDIM; db += 32) {
            __syncthreads();
            #pragma unroll
            for (int r = 0; r < 8; r++) {
                int k  = warp * 32 + r * 4 + ksub;
                int kx = k ^ d16;                            // swizzle within 32-k window
                ks[(d16 + 0) * KSTR2 + kx] = pf[r].x;
                ks[(d16 + 1) * KSTR2 + kx] = pf[r].y;
                ks[(d16 + 2) * KSTR2 + kx] = pf[r].z;
                ks[(d16 + 3) * KSTR2 + kx] = pf[r].w;
            }
            // prefetch next (kb,db) slice — hidden under compute below
            {
                int ndb = db + 32, nkb = kb;
                if (ndb == DDIM) { ndb = 0; nkb += 512; }
                if (nkb < SLEN) {
                    const float* src = Kb + (size_t)(nkb + kbase) * DDIM + ndb + d16;
                    #pragma unroll
                    for (int r = 0; r < 8; r++)
                        pf[r] = *(const float4*)(src + (size_t)(r * 4) * DDIM);
                }
            }
            __syncthreads();
            #pragma unroll
            for (int dd = 0; dd < 32; dd++) {
                int f = dd & 0x1C;                           // 4*(dd>>2), warp-uniform
                float4 qv = *(const float4*)(qT + (db + dd) * QTSTR + qg * 4);   // broadcast
                float4 kv = *(const float4*)(ks + dd * KSTR2 + (kg4 ^ f));       // conflict-free
                fma4(a0, qv.x, kv);
                fma4(a1, qv.y, kv);
                fma4(a2, qv.z, kv);
                fma4(a3, qv.w, kv);
            }
        }
        *(float4*)(zsh + (qg * 4 + 0) * ZSTR + kb + kg4) = a0;
        *(float4*)(zsh + (qg * 4 + 1) * ZSTR + kb + kg4) = a1;
        *(float4*)(zsh + (qg * 4 + 2) * ZSTR + kb + kg4) = a2;
        *(float4*)(zsh + (qg * 4 + 3) * ZSTR + kb + kg4) = a3;
    }
    __syncthreads();

    // prefetch first V tile (vb=0) — hidden under the whole bisection phase
    #pragma unroll
    for (int r = 0; r < 8; r++)
        pf[r] = *(const float4*)(Vb + (size_t)(tid + r * 512) * 4);

    // =========================== Phase 2: bisection (one warp per row) ===========================
    {
        const int row = warp;      // 0..15
        float* zrow = zsh + row * ZSTR;

        float4 zr[16];
        #pragma unroll
        for (int j = 0; j < 16; j++)
            zr[j] = *(const float4*)(zrow + (j * 32 + lane) * 4);

        float m = zr[0].x;
        #pragma unroll
        for (int j = 0; j < 16; j++)
            m = fmaxf(m, fmaxf(fmaxf(zr[j].x, zr[j].y), fmaxf(zr[j].z, zr[j].w)));
        #pragma unroll
        for (int o = 16; o >= 1; o >>= 1)
            m = fmaxf(m, __shfl_xor_sync(0xffffffffu, m, o));

        float lo = m - 1.0f;
        float hi = m - 0.02209708691207961f;   // 2048^(1-1.5)
        float tau = 0.5f * (lo + hi);

        for (int it = 0; it < NITER; it++) {
            tau = 0.5f * (lo + hi);
            float s0 = 0.f, s1 = 0.f, s2 = 0.f, s3 = 0.f;
            #pragma unroll
            for (int j = 0; j < 16; j++) {
                float t0 = fmaxf(zr[j].x - tau, 0.f);
                float t1 = fmaxf(zr[j].y - tau, 0.f);
                float t2 = fmaxf(zr[j].z - tau, 0.f);
                float t3 = fmaxf(zr[j].w - tau, 0.f);
                s0 += t0 * t0; s1 += t1 * t1; s2 += t2 * t2; s3 += t3 * t3;
            }
            float s = (s0 + s1) + (s2 + s3);
            #pragma unroll
            for (int o = 16; o >= 1; o >>= 1)
                s += __shfl_xor_sync(0xffffffffu, s, o);
            if (s >= 1.0f) lo = tau; else hi = tau;
        }

        // final p, Z with last tau (matches reference)
        float s0 = 0.f, s1 = 0.f, s2 = 0.f, s3 = 0.f;
        #pragma unroll
        for (int j = 0; j < 16; j++) {
            float4 p;
            p.x = fmaxf(zr[j].x - tau, 0.f); p.x *= p.x;
            p.y = fmaxf(zr[j].y - tau, 0.f); p.y *= p.y;
            p.z = fmaxf(zr[j].z - tau, 0.f); p.z *= p.z;
            p.w = fmaxf(zr[j].w - tau, 0.f); p.w *= p.w;
            s0 += p.x; s1 += p.y; s2 += p.z; s3 += p.w;
            zr[j] = p;
        }
        float Zs = (s0 + s1) + (s2 + s3);
        #pragma unroll
        for (int o = 16; o >= 1; o >>= 1)
            Zs += __shfl_xor_sync(0xffffffffu, Zs, o);
        float invZ = 1.0f / Zs;

        #pragma unroll
        for (int j = 0; j < 16; j++) {
            float4 w;
            w.x = zr[j].x * invZ; w.y = zr[j].y * invZ;
            w.z = zr[j].z * invZ; w.w = zr[j].w * invZ;
            *(float4*)(zrow + (j * 32 + lane) * 4) = w;
        }
    }

    // =========================== Phase 3: PV ===========================
    {
        float* vs = ks;                    // reuse: 128 x 128 floats = 16384 (fits in 16512)
        const int qg3   = warp >> 3;       // 0..1 -> 8 q rows each
        const int kpart = warp & 7;        // 0..7, warp-constant
        const int dg    = lane;            // 0..31 -> 4 d cols

        float4 o[8];
        #pragma unroll
        for (int qi = 0; qi < 8; qi++) o[qi] = make_float4(0.f, 0.f, 0.f, 0.f);

        for (int vb = 0; vb < SLEN; vb += 128) {
            __syncthreads();   // prev tile consumed (and, first iter, w stores visible)
            #pragma unroll
            for (int r = 0; r < 8; r++)
                ((float4*)vs)[tid + r * 512] = pf[r];
            // prefetch next V tile — hidden under compute below
            if (vb + 128 < SLEN) {
                const float* src = Vb + (size_t)(vb + 128) * DDIM + tid * 4;
                #pragma unroll
                for (int r = 0; r < 8; r++)
                    pf[r] = *(const float4*)(src + r * 2048);
            }
            __syncthreads();

            #pragma unroll
            for (int g = 0; g < 4; g++) {
                int k0 = (g * 8 + kpart) * 4;
                const float* zp = zsh + vb + k0;
                float4 v0 = *(const float4*)(vs + (k0 + 0) * DDIM + dg * 4);
                float4 v1 = *(const float4*)(vs + (k0 + 1) * DDIM + dg * 4);
                float4 v2 = *(const float4*)(vs + (k0 + 2) * DDIM + dg * 4);
                float4 v3 = *(const float4*)(vs + (k0 + 3) * DDIM + dg * 4);
                #pragma unroll
                for (int qi = 0; qi < 8; qi++) {
                    float4 w = *(const float4*)(zp + (qg3 * 8 + qi) * ZSTR);  // broadcast
                    fma4(o[qi], w.x, v0); fma4(o[qi], w.y, v1);
                    fma4(o[qi], w.z, v2); fma4(o[qi], w.w, v3);
                }
            }
        }

        // ---- 3-stage tree reduction of 8 k-partitions via SMEM (float4 slots) ----
        float4* red = (float4*)vs;
        const int base = qg3 * 32 + dg;    // 0..63 (qg3 folded in)

        __syncthreads();
        if (kpart >= 4) {
            int slot = (kpart - 4) * 64 + base;                 // 0..255
            #pragma unroll
            for (int qi = 0; qi < 8; qi++) red[slot + qi * 256] = o[qi];
        }
        __syncthreads();
        if (kpart < 4) {
            int slot = kpart * 64 + base;
            #pragma unroll
            for (int qi = 0; qi < 8; qi++) add4(o[qi], red[slot + qi * 256]);
        }
        __syncthreads();
        if (kpart == 2 || kpart == 3) {
            int slot = (kpart - 2) * 64 + base;                 // 0..127
            #pragma unroll
            for (int qi = 0; qi < 8; qi++) red[slot + qi * 256] = o[qi];
        }
        __syncthreads();
        if (kpart < 2) {
            int slot = kpart * 64 + base;
            #pragma unroll
            for (int qi = 0; qi < 8; qi++) add4(o[qi], red[slot + qi * 256]);
        }
        __syncthreads();
        if (kpart == 1) {
            #pragma unroll
            for (int qi = 0; qi < 8; qi++) red[base + qi * 256] = o[qi];
        }
        __syncthreads();
        if (kpart == 0) {
            #pragma unroll
            for (int qi = 0; qi < 8; qi++) {
                add4(o[qi], red[base + qi * 256]);
                *(float4*)(Ob + (qg3 * 8 + qi) * DDIM + dg * 4) = o[qi];
            }
        }
    }
}

extern "C" void kernel_launch(void* const* d_in, const int* in_sizes, int n_in,
                              void* d_out, int out_size) {
    const float* Q = (const float*)d_in[0];
    const float* K = (const float*)d_in[1];
    const float* V = (const float*)d_in[2];
    float* O = (float*)d_out;

    const int B = in_sizes[0] / (SLEN * DDIM);   // 8
    const size_t smem = (size_t)(TQ * ZSTR + 32 * KSTR2 + 128 * QTSTR) * sizeof(float); // 207,616 B

    cudaFuncSetAttribute(entmax_attn_kernel,
                         cudaFuncAttributeMaxDynamicSharedMemorySize, (int)smem);

    dim3 grid(SLEN / TQ, B);
    entmax_attn_kernel<<<grid, NTHR, smem>>>(Q, K, V, O);
}